// round 4
// baseline (speedup 1.0000x reference)
#include <cuda_runtime.h>
#include <math.h>

// Problem constants
#define NB 16        // B = b*h
#define TLEN 4096    // sequence length
#define NHASH 8
#define NBUCK 64     // local buckets per round
#define NGBUCK 512   // global buckets per B-row
#define CHUNKS 512   // chunks per B-row
#define CS 64        // chunk size
#define E 64         // head dim
#define STR 68       // smem row stride for 64-wide rows (16B-aligned, conflict-free)
#define PSTR 132     // smem row stride for 128-wide prob rows (16B-aligned)
#define VSTR 132     // svT row stride (16B-aligned, conflict-free LDS.128)

// Packed fp32x2 FMA (Blackwell FFMA2) — only reachable via PTX fma.rn.f32x2
#define FFMA2(d, a, b) asm("fma.rn.f32x2 %0, %1, %2, %0;" : "+l"(d) : "l"(a), "l"(b))

__device__ __forceinline__ float hadd2(unsigned long long p) {
    unsigned int lo, hi;
    asm("mov.b64 {%0, %1}, %2;" : "=r"(lo), "=r"(hi) : "l"(p));
    return __uint_as_float(lo) + __uint_as_float(hi);
}

// Scratch (device globals — no allocations allowed)
__device__ unsigned char g_buckets[NB * NHASH * TLEN];
__device__ int   g_counts [NB * NGBUCK];
__device__ int   g_offsets[NB * NGBUCK];
__device__ int   g_st     [NB * NHASH * TLEN];
__device__ float g_logits [NB * NHASH * TLEN];
__device__ float g_o      [(size_t)NB * NHASH * TLEN * E];   // 128MB

__global__ void zero_counts_kernel() {
    int i = blockIdx.x * blockDim.x + threadIdx.x;
    if (i < NB * NGBUCK) g_counts[i] = 0;
}

// Block = (B, 64-token group). Rotations staged in smem (transposed), 8 tokens/warp.
__global__ void __launch_bounds__(256, 2) hash_kernel(const float* __restrict__ qk,
                                                      const float* __restrict__ rot) {
    extern __shared__ float hsm[];
    float* srot = hsm;               // 256 rows (nh*32+i) x STR
    float* sq   = srot + 256 * STR;  // 64 tokens x STR

    int tid = threadIdx.x;
    int B  = blockIdx.x >> 6;
    int t0 = (blockIdx.x & 63) << 6;
    int b = B >> 3, hh = B & 7;

    for (int idx = tid; idx < 64 * NHASH * 32; idx += 256) {
        int e = idx >> 8, r = idx & 255;
        srot[r * STR + e] = rot[idx];
    }
    for (int idx = tid; idx < 64 * 16; idx += 256) {
        int tok = idx >> 4, e4 = (idx & 15) << 2;
        const float* q = qk + (((size_t)(b * TLEN + t0 + tok)) * 8 + hh) * E;
        *(float4*)&sq[tok * STR + e4] = *(const float4*)&q[e4];
    }
    __syncthreads();

    int w = tid >> 5, lane = tid & 31;
    int r0 = w * 8;

    for (int nh = 0; nh < NHASH; nh++) {
        unsigned long long acc2[8];
        #pragma unroll
        for (int r = 0; r < 8; r++) acc2[r] = 0ull;
        const float* rrow = &srot[(nh * 32 + lane) * STR];
        #pragma unroll 4
        for (int q = 0; q < 64; q += 4) {
            ulonglong2 rv = *(const ulonglong2*)&rrow[q];
            #pragma unroll
            for (int r = 0; r < 8; r++) {
                ulonglong2 qv = *(const ulonglong2*)&sq[(r0 + r) * STR + q];
                FFMA2(acc2[r], qv.x, rv.x);
                FFMA2(acc2[r], qv.y, rv.y);
            }
        }
        #pragma unroll
        for (int r = 0; r < 8; r++) {
            float a = hadd2(acc2[r]);
            float bestv; int besti;
            if (-a > a) { bestv = -a; besti = lane + 32; }
            else        { bestv =  a; besti = lane; }
            #pragma unroll
            for (int off = 16; off; off >>= 1) {
                float ov = __shfl_down_sync(0xffffffffu, bestv, off);
                int   oi = __shfl_down_sync(0xffffffffu, besti, off);
                if (ov > bestv || (ov == bestv && oi < besti)) { bestv = ov; besti = oi; }
            }
            besti = __shfl_sync(0xffffffffu, besti, 0);
            if (lane == 0) {
                int t = t0 + r0 + r;
                g_buckets[(B * NHASH + nh) * TLEN + t] = (unsigned char)besti;
                atomicAdd(&g_counts[B * NGBUCK + nh * NBUCK + besti], 1);
            }
        }
    }
}

// Exclusive scan over 512 buckets per B
__global__ void scan_kernel() {
    __shared__ int s[NGBUCK];
    int B = blockIdx.x, tid = threadIdx.x;
    s[tid] = g_counts[B * NGBUCK + tid];
    __syncthreads();
    for (int off = 1; off < NGBUCK; off <<= 1) {
        int v = (tid >= off) ? s[tid - off] : 0;
        __syncthreads();
        s[tid] += v;
        __syncthreads();
    }
    g_offsets[B * NGBUCK + tid] = tid ? s[tid - 1] : 0;
}

// Stable counting-sort scatter: block per (B, nh), 256 threads, 16 passes.
__global__ void scatter_kernel() {
    int B = blockIdx.x >> 3, nh = blockIdx.x & 7;
    __shared__ int cnt[NBUCK];
    __shared__ int wcnt[8][NBUCK];
    int tid = threadIdx.x, w = tid >> 5, lane = tid & 31;

    if (tid < NBUCK) cnt[tid] = g_offsets[B * NGBUCK + nh * NBUCK + tid];
    const unsigned char* src = &g_buckets[(B * NHASH + nh) * TLEN];
    int* dst = &g_st[B * (NHASH * TLEN)];

    for (int pass = 0; pass < 16; pass++) {
        wcnt[w][lane] = 0; wcnt[w][lane + 32] = 0;
        __syncthreads();
        int t = pass * 256 + tid;
        int bk = src[t];
        unsigned mask = __match_any_sync(0xffffffffu, bk);
        int rank = __popc(mask & ((1u << lane) - 1u));
        if (rank == 0) wcnt[w][bk] = __popc(mask);
        __syncthreads();
        int pos = cnt[bk] + rank;
        #pragma unroll
        for (int w2 = 0; w2 < 8; w2++)
            if (w2 < w) pos += wcnt[w2][bk];
        dst[pos] = t;
        __syncthreads();
        if (tid < NBUCK) {
            int s = 0;
            #pragma unroll
            for (int w2 = 0; w2 < 8; w2++) s += wcnt[w2][tid];
            cnt[tid] += s;
        }
        __syncthreads();
    }
}

// Block per (B, chunk): 64 queries x 128 keys, FFMA2 f32x2 throughout.
__global__ void __launch_bounds__(256, 2) attn_kernel(const float* __restrict__ qk,
                                                      const float* __restrict__ vv) {
    extern __shared__ float sm[];
    float* sk   = sm;                   // 128 x STR   (keys/queries, row-major)
    float* svT  = sk + 128 * STR;       // 64 x VSTR   (V transposed: svT[e][j])
    float* sp   = svT + 64 * VSTR;      // 64 x PSTR   (unnormalized probs, 128 wide)
    float* invn = sp + 64 * PSTR;       // 128
    __shared__ int stk[128];

    int tid = threadIdx.x;
    int Bq = blockIdx.x >> 9;
    int c  = blockIdx.x & (CHUNKS - 1);
    int cp = (c + CHUNKS - 1) & (CHUNKS - 1);
    int b = Bq >> 3, hh = Bq & 7;

    if (tid < 128) {
        int p = (tid < 64) ? (c * CS + tid) : (cp * CS + tid - 64);
        stk[tid] = g_st[Bq * (NHASH * TLEN) + p];
    }
    __syncthreads();

    int w = tid >> 5, lane = tid & 31;

    // Gather: warp w handles j = (w&3)*32 + lane, e-range by w>>2.
    {
        int j = ((w & 3) << 5) + lane;
        int e0 = (w >> 2) << 5;
        size_t base = (((size_t)(b * TLEN + stk[j])) * 8 + hh) * E;
        #pragma unroll
        for (int ee = 0; ee < 32; ee += 4) {
            int e4 = e0 + ee;
            float4 kq = *(const float4*)&qk[base + e4];
            float4 v4 = *(const float4*)&vv[base + e4];
            *(float4*)&sk[j * STR + e4] = kq;
            svT[(e4 + 0) * VSTR + j] = v4.x;
            svT[(e4 + 1) * VSTR + j] = v4.y;
            svT[(e4 + 2) * VSTR + j] = v4.z;
            svT[(e4 + 3) * VSTR + j] = v4.w;
        }
    }
    __syncthreads();

    if (tid < 128) {
        float ss = 0.f;
        #pragma unroll
        for (int q = 0; q < E; q += 4) {
            float4 x = *(const float4*)&sk[tid * STR + q];
            ss = fmaf(x.x, x.x, fmaf(x.y, x.y, fmaf(x.z, x.z, fmaf(x.w, x.w, ss))));
        }
        invn[tid] = 1.f / fmaxf(sqrtf(ss), 1e-12f);
    }
    __syncthreads();

    int i0 = w * 8;
    int nh = c >> 6;

    // ---- QK with FFMA2: pair across e; two col-passes to bound registers ----
    float d[8][4];
    #pragma unroll
    for (int half = 0; half < 2; half++) {
        int c0 = lane + half * 64, c1 = lane + 32 + half * 64;
        unsigned long long acc2[8][2];
        #pragma unroll
        for (int r = 0; r < 8; r++) { acc2[r][0] = 0ull; acc2[r][1] = 0ull; }
        #pragma unroll 4
        for (int q = 0; q < 64; q += 4) {
            ulonglong2 k0 = *(const ulonglong2*)&sk[c0 * STR + q];
            ulonglong2 k1 = *(const ulonglong2*)&sk[c1 * STR + q];
            #pragma unroll
            for (int r = 0; r < 8; r++) {
                ulonglong2 qr = *(const ulonglong2*)&sk[(i0 + r) * STR + q];
                FFMA2(acc2[r][0], qr.x, k0.x);
                FFMA2(acc2[r][0], qr.y, k0.y);
                FFMA2(acc2[r][1], qr.x, k1.x);
                FFMA2(acc2[r][1], qr.y, k1.y);
            }
        }
        #pragma unroll
        for (int r = 0; r < 8; r++) {
            d[r][half * 2]     = hadd2(acc2[r][0]);
            d[r][half * 2 + 1] = hadd2(acc2[r][1]);
        }
    }

    float in0 = invn[lane], in1 = invn[lane+32], in2 = invn[lane+64], in3 = invn[lane+96];
    int   tj0 = stk[lane],  tj1 = stk[lane+32],  tj2 = stk[lane+64],  tj3 = stk[lane+96];

    float lse[8], invs[8]; int tirow[8];
    #pragma unroll
    for (int r = 0; r < 8; r++) {
        int ti = stk[i0 + r]; tirow[r] = ti;
        float d0 = d[r][0]*in0, d1 = d[r][1]*in1, d2 = d[r][2]*in2, d3 = d[r][3]*in3;
        if (tj0 == ti) d0 = -50000.f;
        if (tj1 == ti) d1 = -50000.f;
        if (tj2 == ti) d2 = -50000.f;
        if (tj3 == ti) d3 = -50000.f;

        float mx = fmaxf(fmaxf(d0, d1), fmaxf(d2, d3));
        #pragma unroll
        for (int off = 16; off; off >>= 1) mx = fmaxf(mx, __shfl_xor_sync(0xffffffffu, mx, off));
        float e0 = __expf(d0 - mx), e1 = __expf(d1 - mx), e2 = __expf(d2 - mx), e3 = __expf(d3 - mx);
        float s = e0 + e1 + e2 + e3;
        #pragma unroll
        for (int off = 16; off; off >>= 1) s += __shfl_xor_sync(0xffffffffu, s, off);
        // store UNNORMALIZED exp; fold 1/s into the PV epilogue
        sp[(i0 + r) * PSTR + lane     ] = e0;
        sp[(i0 + r) * PSTR + lane + 32] = e1;
        sp[(i0 + r) * PSTR + lane + 64] = e2;
        sp[(i0 + r) * PSTR + lane + 96] = e3;
        invs[r] = 1.f / s;
        lse[r] = mx + __logf(s);
    }
    __syncwarp();

    // ---- PV with FFMA2: pair across j (p contiguous, V transposed) ----
    unsigned long long accp[8][2];
    #pragma unroll
    for (int r = 0; r < 8; r++) { accp[r][0] = 0ull; accp[r][1] = 0ull; }

    #pragma unroll 4
    for (int j2 = 0; j2 < 128; j2 += 4) {
        ulonglong2 va = *(const ulonglong2*)&svT[lane * VSTR + j2];
        ulonglong2 vb = *(const ulonglong2*)&svT[(lane + 32) * VSTR + j2];
        #pragma unroll
        for (int r = 0; r < 8; r++) {
            ulonglong2 p4 = *(const ulonglong2*)&sp[(i0 + r) * PSTR + j2];
            FFMA2(accp[r][0], p4.x, va.x);
            FFMA2(accp[r][0], p4.y, va.y);
            FFMA2(accp[r][1], p4.x, vb.x);
            FFMA2(accp[r][1], p4.y, vb.y);
        }
    }

    #pragma unroll
    for (int r = 0; r < 8; r++) {
        float a0 = hadd2(accp[r][0]) * invs[r];
        float a1 = hadd2(accp[r][1]) * invs[r];
        size_t orow = ((size_t)((Bq * NHASH + nh) * TLEN + tirow[r])) * E;
        g_o[orow + lane]      = a0;
        g_o[orow + lane + 32] = a1;
        if (lane == 0) g_logits[(Bq * NHASH + nh) * TLEN + tirow[r]] = lse[r];
    }
}

// Combine rounds: softmax over 8 per-round lse's, weighted sum (float4 per thread)
__global__ void combine_kernel(float* __restrict__ out) {
    int gid = blockIdx.x * blockDim.x + threadIdx.x;   // NB*TLEN*16 threads
    int d4 = (gid & 15) << 2;
    int token = gid >> 4;                               // 0..65535
    int B = token >> 12, t = token & (TLEN - 1);

    float l[NHASH];
    float mx = -INFINITY;
    #pragma unroll
    for (int nh = 0; nh < NHASH; nh++) {
        l[nh] = g_logits[(B * NHASH + nh) * TLEN + t];
        mx = fmaxf(mx, l[nh]);
    }
    float s = 0.f;
    #pragma unroll
    for (int nh = 0; nh < NHASH; nh++) { l[nh] = __expf(l[nh] - mx); s += l[nh]; }
    float inv = 1.f / s;
    float4 acc = make_float4(0.f, 0.f, 0.f, 0.f);
    #pragma unroll
    for (int nh = 0; nh < NHASH; nh++) {
        float wgt = l[nh] * inv;
        float4 o4 = *(const float4*)&g_o[((size_t)((B * NHASH + nh) * TLEN + t)) * E + d4];
        acc.x = fmaf(wgt, o4.x, acc.x);
        acc.y = fmaf(wgt, o4.y, acc.y);
        acc.z = fmaf(wgt, o4.z, acc.z);
        acc.w = fmaf(wgt, o4.w, acc.w);
    }
    *(float4*)&out[((size_t)token) * E + d4] = acc;
}

extern "C" void kernel_launch(void* const* d_in, const int* in_sizes, int n_in,
                              void* d_out, int out_size) {
    const float* qk  = (const float*)d_in[0];
    // d_in[1] = k is unused by the reference (shared-QK attention)
    const float* v   = (const float*)d_in[2];
    const float* rot = (const float*)d_in[3];
    float* out = (float*)d_out;

    const int attn_smem = (128 * STR + 64 * VSTR + 64 * PSTR + 128) * (int)sizeof(float); // 102912
    const int hash_smem = (256 * STR + 64 * STR) * (int)sizeof(float);                     // 87040
    cudaFuncSetAttribute(attn_kernel, cudaFuncAttributeMaxDynamicSharedMemorySize, attn_smem);
    cudaFuncSetAttribute(hash_kernel, cudaFuncAttributeMaxDynamicSharedMemorySize, hash_smem);

    zero_counts_kernel<<<32, 256>>>();
    hash_kernel<<<NB * 64, 256, hash_smem>>>(qk, rot);
    scan_kernel<<<NB, NGBUCK>>>();
    scatter_kernel<<<NB * NHASH, 256>>>();
    attn_kernel<<<NB * CHUNKS, 256, attn_smem>>>(qk, v);
    combine_kernel<<<NB * TLEN * E / 4 / 256, 256>>>(out);
}

// round 5
// speedup vs baseline: 1.2210x; 1.2210x over previous
#include <cuda_runtime.h>
#include <math.h>

// Problem constants
#define NB 16        // B = b*h
#define TLEN 4096    // sequence length
#define NHASH 8
#define NBUCK 64     // local buckets per round
#define NGBUCK 512   // global buckets per B-row
#define CHUNKS 512   // chunks per B-row
#define CS 64        // chunk size
#define E 64         // head dim
#define STR 68       // smem row stride for 64-wide rows (float4-aligned, conflict-free)
#define PSTR 132     // smem row stride for 128-wide prob rows (float4-aligned)

// Scratch (device globals — no allocations allowed)
__device__ unsigned char g_buckets[NB * NHASH * TLEN];       // local bucket per (B,nh,t)
__device__ int   g_counts [NB * NGBUCK];
__device__ int   g_offsets[NB * NGBUCK];
__device__ int   g_st     [NB * NHASH * TLEN];               // sorted token ids
__device__ float g_logits [NB * NHASH * TLEN];               // per-round lse at (B,nh,t)
__device__ float g_o      [(size_t)NB * NHASH * TLEN * E];   // per-round outputs (128MB)

__global__ void zero_counts_kernel() {
    int i = blockIdx.x * blockDim.x + threadIdx.x;
    if (i < NB * NGBUCK) g_counts[i] = 0;
}

// Block = (B, 64-token group). Rotations staged in smem (transposed), 8 tokens/warp.
__global__ void __launch_bounds__(256, 2) hash_kernel(const float* __restrict__ qk,
                                                      const float* __restrict__ rot) {
    extern __shared__ float hsm[];
    float* srot = hsm;               // 256 rows (nh*32+i) x STR, cols = e
    float* sq   = srot + 256 * STR;  // 64 tokens x STR

    int tid = threadIdx.x;
    int B  = blockIdx.x >> 6;
    int t0 = (blockIdx.x & 63) << 6;
    int b = B >> 3, hh = B & 7;

    // Stage rotations transposed: srot[(nh*32+i)][e] = rot[e*256 + nh*32+i]
    for (int idx = tid; idx < 64 * NHASH * 32; idx += 256) {
        int e = idx >> 8, r = idx & 255;
        srot[r * STR + e] = rot[idx];
    }
    // Stage 64 query rows (coalesced float4)
    for (int idx = tid; idx < 64 * 16; idx += 256) {
        int tok = idx >> 4, e4 = (idx & 15) << 2;
        const float* q = qk + (((size_t)(b * TLEN + t0 + tok)) * 8 + hh) * E;
        *(float4*)&sq[tok * STR + e4] = *(const float4*)&q[e4];
    }
    __syncthreads();

    int w = tid >> 5, lane = tid & 31;
    int r0 = w * 8;   // this warp's 8 tokens

    for (int nh = 0; nh < NHASH; nh++) {
        float acc[8];
        #pragma unroll
        for (int r = 0; r < 8; r++) acc[r] = 0.f;
        const float* rrow = &srot[(nh * 32 + lane) * STR];
        #pragma unroll 4
        for (int e4 = 0; e4 < 64; e4 += 4) {
            float4 rv = *(const float4*)&rrow[e4];
            #pragma unroll
            for (int r = 0; r < 8; r++) {
                float4 qv = *(const float4*)&sq[(r0 + r) * STR + e4];
                acc[r] = fmaf(qv.x, rv.x, fmaf(qv.y, rv.y, fmaf(qv.z, rv.z, fmaf(qv.w, rv.w, acc[r]))));
            }
        }
        #pragma unroll
        for (int r = 0; r < 8; r++) {
            float a = acc[r];
            float bestv; int besti;
            if (-a > a) { bestv = -a; besti = lane + 32; }
            else        { bestv =  a; besti = lane; }
            #pragma unroll
            for (int off = 16; off; off >>= 1) {
                float ov = __shfl_down_sync(0xffffffffu, bestv, off);
                int   oi = __shfl_down_sync(0xffffffffu, besti, off);
                if (ov > bestv || (ov == bestv && oi < besti)) { bestv = ov; besti = oi; }
            }
            besti = __shfl_sync(0xffffffffu, besti, 0);
            if (lane == 0) {
                int t = t0 + r0 + r;
                g_buckets[(B * NHASH + nh) * TLEN + t] = (unsigned char)besti;
                atomicAdd(&g_counts[B * NGBUCK + nh * NBUCK + besti], 1);
            }
        }
    }
}

// Exclusive scan over 512 buckets per B (Hillis-Steele in shared)
__global__ void scan_kernel() {
    __shared__ int s[NGBUCK];
    int B = blockIdx.x, tid = threadIdx.x;
    s[tid] = g_counts[B * NGBUCK + tid];
    __syncthreads();
    for (int off = 1; off < NGBUCK; off <<= 1) {
        int v = (tid >= off) ? s[tid - off] : 0;
        __syncthreads();
        s[tid] += v;
        __syncthreads();
    }
    g_offsets[B * NGBUCK + tid] = tid ? s[tid - 1] : 0;
}

// Stable counting-sort scatter: block per (B, nh), 256 threads, 16 passes.
__global__ void scatter_kernel() {
    int B = blockIdx.x >> 3, nh = blockIdx.x & 7;
    __shared__ int cnt[NBUCK];
    __shared__ int wcnt[8][NBUCK];
    int tid = threadIdx.x, w = tid >> 5, lane = tid & 31;

    if (tid < NBUCK) cnt[tid] = g_offsets[B * NGBUCK + nh * NBUCK + tid];
    const unsigned char* src = &g_buckets[(B * NHASH + nh) * TLEN];
    int* dst = &g_st[B * (NHASH * TLEN)];

    for (int pass = 0; pass < 16; pass++) {
        wcnt[w][lane] = 0; wcnt[w][lane + 32] = 0;
        __syncthreads();
        int t = pass * 256 + tid;
        int bk = src[t];
        unsigned mask = __match_any_sync(0xffffffffu, bk);
        int rank = __popc(mask & ((1u << lane) - 1u));
        if (rank == 0) wcnt[w][bk] = __popc(mask);
        __syncthreads();
        int pos = cnt[bk] + rank;
        #pragma unroll
        for (int w2 = 0; w2 < 8; w2++)
            if (w2 < w) pos += wcnt[w2][bk];
        dst[pos] = t;
        __syncthreads();
        if (tid < NBUCK) {
            int s = 0;
            #pragma unroll
            for (int w2 = 0; w2 < 8; w2++) s += wcnt[w2][tid];
            cnt[tid] += s;
        }
        __syncthreads();
    }
}

// Block per (B, chunk): 64 queries x 128 keys. Register-tiled: warp = 8 rows,
// thread = 4 key-cols {l, l+32, l+64, l+96}. float4 smem. Fast exp/log.
__global__ void __launch_bounds__(256, 2) attn_kernel(const float* __restrict__ qk,
                                                      const float* __restrict__ vv) {
    extern __shared__ float sm[];
    float* sk   = sm;                   // 128 x STR
    float* sv   = sk + 128 * STR;       // 128 x STR
    float* sp   = sv + 128 * STR;       // 64 x PSTR (unnormalized probs, 128 wide)
    float* invn = sp + 64 * PSTR;       // 128
    __shared__ int stk[128];

    int tid = threadIdx.x;
    int Bq = blockIdx.x >> 9;
    int c  = blockIdx.x & (CHUNKS - 1);
    int cp = (c + CHUNKS - 1) & (CHUNKS - 1);
    int b = Bq >> 3, hh = Bq & 7;

    if (tid < 128) {
        int p = (tid < 64) ? (c * CS + tid) : (cp * CS + tid - 64);
        stk[tid] = g_st[Bq * (NHASH * TLEN) + p];
    }
    __syncthreads();

    // Gather 128 rows (coalesced float4)
    {
        int e4 = (tid & 15) << 2;
        for (int j = tid >> 4; j < 128; j += 16) {
            size_t base = (((size_t)(b * TLEN + stk[j])) * 8 + hh) * E;
            *(float4*)&sk[j * STR + e4] = *(const float4*)&qk[base + e4];
            *(float4*)&sv[j * STR + e4] = *(const float4*)&vv[base + e4];
        }
    }
    __syncthreads();

    if (tid < 128) {
        float ss = 0.f;
        #pragma unroll
        for (int q = 0; q < E; q += 4) {
            float4 x = *(const float4*)&sk[tid * STR + q];
            ss = fmaf(x.x, x.x, fmaf(x.y, x.y, fmaf(x.z, x.z, fmaf(x.w, x.w, ss))));
        }
        invn[tid] = 1.f / fmaxf(sqrtf(ss), 1e-12f);
    }
    __syncthreads();

    int w = tid >> 5, lane = tid & 31;
    int i0 = w * 8;
    int nh = c >> 6;

    // ---- QK: 8 rows x 4 cols register tile ----
    float acc[8][4];
    #pragma unroll
    for (int r = 0; r < 8; r++) { acc[r][0]=0.f; acc[r][1]=0.f; acc[r][2]=0.f; acc[r][3]=0.f; }

    #pragma unroll 4
    for (int q = 0; q < E; q += 4) {
        float4 k0 = *(const float4*)&sk[(lane      ) * STR + q];
        float4 k1 = *(const float4*)&sk[(lane + 32 ) * STR + q];
        float4 k2 = *(const float4*)&sk[(lane + 64 ) * STR + q];
        float4 k3 = *(const float4*)&sk[(lane + 96 ) * STR + q];
        #pragma unroll
        for (int r = 0; r < 8; r++) {
            float4 qv = *(const float4*)&sk[(i0 + r) * STR + q];
            acc[r][0] = fmaf(qv.x,k0.x, fmaf(qv.y,k0.y, fmaf(qv.z,k0.z, fmaf(qv.w,k0.w, acc[r][0]))));
            acc[r][1] = fmaf(qv.x,k1.x, fmaf(qv.y,k1.y, fmaf(qv.z,k1.z, fmaf(qv.w,k1.w, acc[r][1]))));
            acc[r][2] = fmaf(qv.x,k2.x, fmaf(qv.y,k2.y, fmaf(qv.z,k2.z, fmaf(qv.w,k2.w, acc[r][2]))));
            acc[r][3] = fmaf(qv.x,k3.x, fmaf(qv.y,k3.y, fmaf(qv.z,k3.z, fmaf(qv.w,k3.w, acc[r][3]))));
        }
    }

    float in0 = invn[lane], in1 = invn[lane+32], in2 = invn[lane+64], in3 = invn[lane+96];
    int   tj0 = stk[lane],  tj1 = stk[lane+32],  tj2 = stk[lane+64],  tj3 = stk[lane+96];

    float lse[8], invs[8]; int tirow[8];
    #pragma unroll
    for (int r = 0; r < 8; r++) {
        int ti = stk[i0 + r]; tirow[r] = ti;
        float d0 = acc[r][0]*in0, d1 = acc[r][1]*in1, d2 = acc[r][2]*in2, d3 = acc[r][3]*in3;
        if (tj0 == ti) d0 = -50000.f;
        if (tj1 == ti) d1 = -50000.f;
        if (tj2 == ti) d2 = -50000.f;
        if (tj3 == ti) d3 = -50000.f;

        float mx = fmaxf(fmaxf(d0, d1), fmaxf(d2, d3));
        #pragma unroll
        for (int off = 16; off; off >>= 1) mx = fmaxf(mx, __shfl_xor_sync(0xffffffffu, mx, off));
        float e0 = __expf(d0 - mx), e1 = __expf(d1 - mx), e2 = __expf(d2 - mx), e3 = __expf(d3 - mx);
        float s = e0 + e1 + e2 + e3;
        #pragma unroll
        for (int off = 16; off; off >>= 1) s += __shfl_xor_sync(0xffffffffu, s, off);
        // store UNNORMALIZED exp; 1/s folded into PV epilogue
        sp[(i0 + r) * PSTR + lane     ] = e0;
        sp[(i0 + r) * PSTR + lane + 32] = e1;
        sp[(i0 + r) * PSTR + lane + 64] = e2;
        sp[(i0 + r) * PSTR + lane + 96] = e3;
        invs[r] = 1.f / s;
        lse[r] = mx + __logf(s);
    }
    __syncwarp();

    // ---- PV: 8 rows x 2 dims per thread ----
    float a0[8], a1[8];
    #pragma unroll
    for (int r = 0; r < 8; r++) { a0[r] = 0.f; a1[r] = 0.f; }

    #pragma unroll 2
    for (int j4 = 0; j4 < 128; j4 += 4) {
        float4 p4[8];
        #pragma unroll
        for (int r = 0; r < 8; r++) p4[r] = *(const float4*)&sp[(i0 + r) * PSTR + j4];

        float v0, v1;
        v0 = sv[(j4+0)*STR + lane]; v1 = sv[(j4+0)*STR + lane + 32];
        #pragma unroll
        for (int r = 0; r < 8; r++) { a0[r] = fmaf(p4[r].x, v0, a0[r]); a1[r] = fmaf(p4[r].x, v1, a1[r]); }
        v0 = sv[(j4+1)*STR + lane]; v1 = sv[(j4+1)*STR + lane + 32];
        #pragma unroll
        for (int r = 0; r < 8; r++) { a0[r] = fmaf(p4[r].y, v0, a0[r]); a1[r] = fmaf(p4[r].y, v1, a1[r]); }
        v0 = sv[(j4+2)*STR + lane]; v1 = sv[(j4+2)*STR + lane + 32];
        #pragma unroll
        for (int r = 0; r < 8; r++) { a0[r] = fmaf(p4[r].z, v0, a0[r]); a1[r] = fmaf(p4[r].z, v1, a1[r]); }
        v0 = sv[(j4+3)*STR + lane]; v1 = sv[(j4+3)*STR + lane + 32];
        #pragma unroll
        for (int r = 0; r < 8; r++) { a0[r] = fmaf(p4[r].w, v0, a0[r]); a1[r] = fmaf(p4[r].w, v1, a1[r]); }
    }

    #pragma unroll
    for (int r = 0; r < 8; r++) {
        size_t orow = ((size_t)((Bq * NHASH + nh) * TLEN + tirow[r])) * E;
        g_o[orow + lane]      = a0[r] * invs[r];
        g_o[orow + lane + 32] = a1[r] * invs[r];
        if (lane == 0) g_logits[(Bq * NHASH + nh) * TLEN + tirow[r]] = lse[r];
    }
}

// Combine rounds: softmax over 8 per-round lse's, weighted sum (float4 per thread)
__global__ void combine_kernel(float* __restrict__ out) {
    int gid = blockIdx.x * blockDim.x + threadIdx.x;   // NB*TLEN*16 threads
    int d4 = (gid & 15) << 2;
    int token = gid >> 4;                               // 0..65535
    int B = token >> 12, t = token & (TLEN - 1);

    float l[NHASH];
    float mx = -INFINITY;
    #pragma unroll
    for (int nh = 0; nh < NHASH; nh++) {
        l[nh] = g_logits[(B * NHASH + nh) * TLEN + t];
        mx = fmaxf(mx, l[nh]);
    }
    float s = 0.f;
    #pragma unroll
    for (int nh = 0; nh < NHASH; nh++) { l[nh] = __expf(l[nh] - mx); s += l[nh]; }
    float inv = 1.f / s;
    float4 acc = make_float4(0.f, 0.f, 0.f, 0.f);
    #pragma unroll
    for (int nh = 0; nh < NHASH; nh++) {
        float wgt = l[nh] * inv;
        float4 o4 = *(const float4*)&g_o[((size_t)((B * NHASH + nh) * TLEN + t)) * E + d4];
        acc.x = fmaf(wgt, o4.x, acc.x);
        acc.y = fmaf(wgt, o4.y, acc.y);
        acc.z = fmaf(wgt, o4.z, acc.z);
        acc.w = fmaf(wgt, o4.w, acc.w);
    }
    *(float4*)&out[((size_t)token) * E + d4] = acc;
}

extern "C" void kernel_launch(void* const* d_in, const int* in_sizes, int n_in,
                              void* d_out, int out_size) {
    const float* qk  = (const float*)d_in[0];
    // d_in[1] = k is unused by the reference (shared-QK attention)
    const float* v   = (const float*)d_in[2];
    const float* rot = (const float*)d_in[3];
    float* out = (float*)d_out;

    const int attn_smem = (128 * STR * 2 + 64 * PSTR + 128) * (int)sizeof(float); // 103936
    const int hash_smem = (256 * STR + 64 * STR) * (int)sizeof(float);            // 87040
    cudaFuncSetAttribute(attn_kernel, cudaFuncAttributeMaxDynamicSharedMemorySize, attn_smem);
    cudaFuncSetAttribute(hash_kernel, cudaFuncAttributeMaxDynamicSharedMemorySize, hash_smem);

    zero_counts_kernel<<<32, 256>>>();
    hash_kernel<<<NB * 64, 256, hash_smem>>>(qk, rot);
    scan_kernel<<<NB, NGBUCK>>>();
    scatter_kernel<<<NB * NHASH, 256>>>();
    attn_kernel<<<NB * CHUNKS, 256, attn_smem>>>(qk, v);
    combine_kernel<<<NB * TLEN * E / 4 / 256, 256>>>(out);
}

// round 7
// speedup vs baseline: 2.0061x; 1.6430x over previous
#include <cuda_runtime.h>
#include <cuda_bf16.h>
#include <stdint.h>
#include <cstdint>
#include <math.h>

// Problem constants
#define NB 16        // B = b*h
#define TLEN 4096    // sequence length
#define NHASH 8
#define NBUCK 64     // local buckets per round
#define NGBUCK 512   // global buckets per B-row
#define CHUNKS 512   // chunks per B-row
#define CS 64        // chunk size
#define E 64         // head dim
#define STR 68       // smem row stride (floats) for hash kernel

typedef unsigned int u32;

// Scratch (device globals — no allocations allowed)
__device__ unsigned char g_buckets[NB * NHASH * TLEN];
__device__ int   g_counts [NB * NGBUCK];
__device__ int   g_offsets[NB * NGBUCK];
__device__ int   g_st     [NB * NHASH * TLEN];
__device__ float g_logits [NB * NHASH * TLEN];
__device__ float g_o      [(size_t)NB * NHASH * TLEN * E];   // 128MB

__global__ void zero_counts_kernel() {
    int i = blockIdx.x * blockDim.x + threadIdx.x;
    if (i < NB * NGBUCK) g_counts[i] = 0;
}

// ---------------- hash (unchanged from R5) ----------------
__global__ void __launch_bounds__(256, 2) hash_kernel(const float* __restrict__ qk,
                                                      const float* __restrict__ rot) {
    extern __shared__ float hsm[];
    float* srot = hsm;               // 256 rows x STR
    float* sq   = srot + 256 * STR;  // 64 tokens x STR

    int tid = threadIdx.x;
    int B  = blockIdx.x >> 6;
    int t0 = (blockIdx.x & 63) << 6;
    int b = B >> 3, hh = B & 7;

    for (int idx = tid; idx < 64 * NHASH * 32; idx += 256) {
        int e = idx >> 8, r = idx & 255;
        srot[r * STR + e] = rot[idx];
    }
    for (int idx = tid; idx < 64 * 16; idx += 256) {
        int tok = idx >> 4, e4 = (idx & 15) << 2;
        const float* q = qk + (((size_t)(b * TLEN + t0 + tok)) * 8 + hh) * E;
        *(float4*)&sq[tok * STR + e4] = *(const float4*)&q[e4];
    }
    __syncthreads();

    int w = tid >> 5, lane = tid & 31;
    int r0 = w * 8;

    for (int nh = 0; nh < NHASH; nh++) {
        float acc[8];
        #pragma unroll
        for (int r = 0; r < 8; r++) acc[r] = 0.f;
        const float* rrow = &srot[(nh * 32 + lane) * STR];
        #pragma unroll 4
        for (int e4 = 0; e4 < 64; e4 += 4) {
            float4 rv = *(const float4*)&rrow[e4];
            #pragma unroll
            for (int r = 0; r < 8; r++) {
                float4 qv = *(const float4*)&sq[(r0 + r) * STR + e4];
                acc[r] = fmaf(qv.x, rv.x, fmaf(qv.y, rv.y, fmaf(qv.z, rv.z, fmaf(qv.w, rv.w, acc[r]))));
            }
        }
        #pragma unroll
        for (int r = 0; r < 8; r++) {
            float a = acc[r];
            float bestv; int besti;
            if (-a > a) { bestv = -a; besti = lane + 32; }
            else        { bestv =  a; besti = lane; }
            #pragma unroll
            for (int off = 16; off; off >>= 1) {
                float ov = __shfl_down_sync(0xffffffffu, bestv, off);
                int   oi = __shfl_down_sync(0xffffffffu, besti, off);
                if (ov > bestv || (ov == bestv && oi < besti)) { bestv = ov; besti = oi; }
            }
            besti = __shfl_sync(0xffffffffu, besti, 0);
            if (lane == 0) {
                int t = t0 + r0 + r;
                g_buckets[(B * NHASH + nh) * TLEN + t] = (unsigned char)besti;
                atomicAdd(&g_counts[B * NGBUCK + nh * NBUCK + besti], 1);
            }
        }
    }
}

__global__ void scan_kernel() {
    __shared__ int s[NGBUCK];
    int B = blockIdx.x, tid = threadIdx.x;
    s[tid] = g_counts[B * NGBUCK + tid];
    __syncthreads();
    for (int off = 1; off < NGBUCK; off <<= 1) {
        int v = (tid >= off) ? s[tid - off] : 0;
        __syncthreads();
        s[tid] += v;
        __syncthreads();
    }
    g_offsets[B * NGBUCK + tid] = tid ? s[tid - 1] : 0;
}

__global__ void scatter_kernel() {
    int B = blockIdx.x >> 3, nh = blockIdx.x & 7;
    __shared__ int cnt[NBUCK];
    __shared__ int wcnt[8][NBUCK];
    int tid = threadIdx.x, w = tid >> 5, lane = tid & 31;

    if (tid < NBUCK) cnt[tid] = g_offsets[B * NGBUCK + nh * NBUCK + tid];
    const unsigned char* src = &g_buckets[(B * NHASH + nh) * TLEN];
    int* dst = &g_st[B * (NHASH * TLEN)];

    for (int pass = 0; pass < 16; pass++) {
        wcnt[w][lane] = 0; wcnt[w][lane + 32] = 0;
        __syncthreads();
        int t = pass * 256 + tid;
        int bk = src[t];
        unsigned mask = __match_any_sync(0xffffffffu, bk);
        int rank = __popc(mask & ((1u << lane) - 1u));
        if (rank == 0) wcnt[w][bk] = __popc(mask);
        __syncthreads();
        int pos = cnt[bk] + rank;
        #pragma unroll
        for (int w2 = 0; w2 < 8; w2++)
            if (w2 < w) pos += wcnt[w2][bk];
        dst[pos] = t;
        __syncthreads();
        if (tid < NBUCK) {
            int s = 0;
            #pragma unroll
            for (int w2 = 0; w2 < 8; w2++) s += wcnt[w2][tid];
            cnt[tid] += s;
        }
        __syncthreads();
    }
}

// ---------------- tensor-core attention ----------------
#define SM_KLO 16384
#define SM_VHI 32768
#define SM_VLO 49152
#define SM_PO  65536
#define SM_INV 82944
#define SM_RDM 83456
#define SM_RDS 83968
#define SM_STK 84480
#define ATTN_SMEM 84992
#define POSTR 68

__device__ __forceinline__ u32 swz(int row, int chunk) {
    return (u32)(row * 128 + (((chunk ^ (row & 7)) & 7) << 4));
}
__device__ __forceinline__ void ldsm_x4(u32* r, u32 addr) {
    asm volatile("ldmatrix.sync.aligned.m8n8.x4.shared.b16 {%0,%1,%2,%3}, [%4];"
                 : "=r"(r[0]), "=r"(r[1]), "=r"(r[2]), "=r"(r[3]) : "r"(addr));
}
__device__ __forceinline__ void ldsm_x4t(u32* r, u32 addr) {
    asm volatile("ldmatrix.sync.aligned.m8n8.x4.trans.shared.b16 {%0,%1,%2,%3}, [%4];"
                 : "=r"(r[0]), "=r"(r[1]), "=r"(r[2]), "=r"(r[3]) : "r"(addr));
}
__device__ __forceinline__ void mma_bf16(float* d, const u32* a, u32 b0, u32 b1) {
    asm volatile("mma.sync.aligned.m16n8k16.row.col.f32.bf16.bf16.f32 "
                 "{%0,%1,%2,%3},{%4,%5,%6,%7},{%8,%9},{%0,%1,%2,%3};"
                 : "+f"(d[0]), "+f"(d[1]), "+f"(d[2]), "+f"(d[3])
                 : "r"(a[0]), "r"(a[1]), "r"(a[2]), "r"(a[3]), "r"(b0), "r"(b1));
}
__device__ __forceinline__ u32 packbf2(float a, float b) {
    __nv_bfloat162 t = __floats2bfloat162_rn(a, b);   // .x = a (low half)
    return *(u32*)&t;
}

__global__ void __launch_bounds__(256, 2) attn_kernel(const float* __restrict__ qk,
                                                      const float* __restrict__ vv) {
    extern __shared__ char smem[];
    float* po   = (float*)(smem + SM_PO);
    float* invn = (float*)(smem + SM_INV);
    float* redm = (float*)(smem + SM_RDM);
    float* reds = (float*)(smem + SM_RDS);
    int*   stk  = (int*)  (smem + SM_STK);

    int tid = threadIdx.x;
    int Bq = blockIdx.x >> 9;
    int c  = blockIdx.x & (CHUNKS - 1);
    int cp = (c + CHUNKS - 1) & (CHUNKS - 1);
    int b = Bq >> 3, hh = Bq & 7;
    int nh = c >> 6;

    if (tid < 128) {
        int p = (tid < 64) ? (c * CS + tid) : (cp * CS + tid - 64);
        stk[tid] = g_st[Bq * (NHASH * TLEN) + p];
    }
    __syncthreads();

    // ---- gather + bf16 hi/lo split + key norms ----
    {
        int seg = tid & 7;              // 8-col segment of a row
        #pragma unroll
        for (int pass = 0; pass < 4; pass++) {
            int j = (tid >> 3) + pass * 32;
            size_t base = (((size_t)(b * TLEN + stk[j])) * 8 + hh) * E + seg * 8;
            float4 q0 = *(const float4*)&qk[base];
            float4 q1 = *(const float4*)&qk[base + 4];
            float4 w0 = *(const float4*)&vv[base];
            float4 w1 = *(const float4*)&vv[base + 4];
            u32 off = swz(j, seg);

            float xq[8] = {q0.x,q0.y,q0.z,q0.w,q1.x,q1.y,q1.z,q1.w};
            float xv[8] = {w0.x,w0.y,w0.z,w0.w,w1.x,w1.y,w1.z,w1.w};
            u32 qh[4], ql[4], vh[4], vl[4];
            #pragma unroll
            for (int i = 0; i < 4; i++) {
                __nv_bfloat16 h0 = __float2bfloat16(xq[2*i]);
                __nv_bfloat16 h1 = __float2bfloat16(xq[2*i+1]);
                qh[i] = packbf2(xq[2*i], xq[2*i+1]);
                ql[i] = packbf2(xq[2*i] - __bfloat162float(h0), xq[2*i+1] - __bfloat162float(h1));
                __nv_bfloat16 g0 = __float2bfloat16(xv[2*i]);
                __nv_bfloat16 g1 = __float2bfloat16(xv[2*i+1]);
                vh[i] = packbf2(xv[2*i], xv[2*i+1]);
                vl[i] = packbf2(xv[2*i] - __bfloat162float(g0), xv[2*i+1] - __bfloat162float(g1));
            }
            *(uint4*)(smem + off)          = make_uint4(qh[0],qh[1],qh[2],qh[3]);
            *(uint4*)(smem + SM_KLO + off) = make_uint4(ql[0],ql[1],ql[2],ql[3]);
            *(uint4*)(smem + SM_VHI + off) = make_uint4(vh[0],vh[1],vh[2],vh[3]);
            *(uint4*)(smem + SM_VLO + off) = make_uint4(vl[0],vl[1],vl[2],vl[3]);

            float ss = 0.f;
            #pragma unroll
            for (int i = 0; i < 8; i++) ss = fmaf(xq[i], xq[i], ss);
            ss += __shfl_xor_sync(0xffffffffu, ss, 1);
            ss += __shfl_xor_sync(0xffffffffu, ss, 2);
            ss += __shfl_xor_sync(0xffffffffu, ss, 4);
            if (seg == 0) invn[j] = 1.f / fmaxf(sqrtf(ss), 1e-12f);
        }
    }
    __syncthreads();

    int w = tid >> 5, lane = tid & 31;
    int wm = w & 3, wn = w >> 2;
    int m0 = wm * 16, n0 = wn * 64;
    int g  = lane >> 3, lr = lane & 7;
    u32 kb = (u32)__cvta_generic_to_shared(smem);

    // ---- QK: D[64q,128k] via 3 split MMAs ----
    float acc[8][4];
    #pragma unroll
    for (int nt = 0; nt < 8; nt++) { acc[nt][0]=0.f; acc[nt][1]=0.f; acc[nt][2]=0.f; acc[nt][3]=0.f; }

    #pragma unroll
    for (int ck = 0; ck < 4; ck++) {
        int arow = m0 + ((g & 1) << 3) + lr;
        u32 aoff = swz(arow, 2 * ck + (g >> 1));
        u32 aH[4], aL[4];
        ldsm_x4(aH, kb + aoff);
        ldsm_x4(aL, kb + SM_KLO + aoff);
        #pragma unroll
        for (int p = 0; p < 4; p++) {
            int brow = n0 + 16 * p + ((g >> 1) << 3) + lr;
            u32 boff = swz(brow, 2 * ck + (g & 1));
            u32 bH[4], bL[4];
            ldsm_x4(bH, kb + boff);
            ldsm_x4(bL, kb + SM_KLO + boff);
            mma_bf16(acc[2*p],   aH, bH[0], bH[1]);
            mma_bf16(acc[2*p+1], aH, bH[2], bH[3]);
            mma_bf16(acc[2*p],   aH, bL[0], bL[1]);
            mma_bf16(acc[2*p+1], aH, bL[2], bL[3]);
            mma_bf16(acc[2*p],   aL, bH[0], bH[1]);
            mma_bf16(acc[2*p+1], aL, bH[2], bH[3]);
        }
    }

    // ---- scale by key inv-norm, self-mask, softmax ----
    int rA = m0 + (lane >> 2), rB = rA + 8;
    int tiA = stk[rA], tiB = stk[rB];
    float mA = -INFINITY, mB = -INFINITY;
    #pragma unroll
    for (int nt = 0; nt < 8; nt++) {
        int c0 = n0 + 8 * nt + 2 * (lane & 3);
        float i0 = invn[c0], i1 = invn[c0 + 1];
        int tc0 = stk[c0], tc1 = stk[c0 + 1];
        acc[nt][0] *= i0; acc[nt][1] *= i1; acc[nt][2] *= i0; acc[nt][3] *= i1;
        if (tc0 == tiA) acc[nt][0] = -50000.f;
        if (tc1 == tiA) acc[nt][1] = -50000.f;
        if (tc0 == tiB) acc[nt][2] = -50000.f;
        if (tc1 == tiB) acc[nt][3] = -50000.f;
        mA = fmaxf(mA, fmaxf(acc[nt][0], acc[nt][1]));
        mB = fmaxf(mB, fmaxf(acc[nt][2], acc[nt][3]));
    }
    mA = fmaxf(mA, __shfl_xor_sync(0xffffffffu, mA, 1));
    mA = fmaxf(mA, __shfl_xor_sync(0xffffffffu, mA, 2));
    mB = fmaxf(mB, __shfl_xor_sync(0xffffffffu, mB, 1));
    mB = fmaxf(mB, __shfl_xor_sync(0xffffffffu, mB, 2));

    int ridx = (wm * 2 + wn) * 16 + (lane >> 2);
    int pidx = (wm * 2 + (1 - wn)) * 16 + (lane >> 2);
    if ((lane & 3) == 0) { redm[ridx] = mA; redm[ridx + 8] = mB; }
    __syncthreads();
    mA = fmaxf(mA, redm[pidx]); mB = fmaxf(mB, redm[pidx + 8]);

    float sA = 0.f, sB = 0.f;
    #pragma unroll
    for (int nt = 0; nt < 8; nt++) {
        acc[nt][0] = __expf(acc[nt][0] - mA);
        acc[nt][1] = __expf(acc[nt][1] - mA);
        acc[nt][2] = __expf(acc[nt][2] - mB);
        acc[nt][3] = __expf(acc[nt][3] - mB);
        sA += acc[nt][0] + acc[nt][1];
        sB += acc[nt][2] + acc[nt][3];
    }
    sA += __shfl_xor_sync(0xffffffffu, sA, 1);
    sA += __shfl_xor_sync(0xffffffffu, sA, 2);
    sB += __shfl_xor_sync(0xffffffffu, sB, 1);
    sB += __shfl_xor_sync(0xffffffffu, sB, 2);
    if ((lane & 3) == 0) { reds[ridx] = sA; reds[ridx + 8] = sB; }
    __syncthreads();
    sA += reds[pidx]; sB += reds[pidx + 8];
    float invsA = 1.f / sA, invsB = 1.f / sB;
    float lseA = mA + __logf(sA), lseB = mB + __logf(sB);

    // ---- P -> bf16 hi/lo fragments (stays in registers) ----
    u32 phA[8], phB[8], plA[8], plB[8];
    #pragma unroll
    for (int nt = 0; nt < 8; nt++) {
        __nv_bfloat16 h0 = __float2bfloat16(acc[nt][0]);
        __nv_bfloat16 h1 = __float2bfloat16(acc[nt][1]);
        __nv_bfloat16 h2 = __float2bfloat16(acc[nt][2]);
        __nv_bfloat16 h3 = __float2bfloat16(acc[nt][3]);
        phA[nt] = packbf2(acc[nt][0], acc[nt][1]);
        phB[nt] = packbf2(acc[nt][2], acc[nt][3]);
        plA[nt] = packbf2(acc[nt][0] - __bfloat162float(h0), acc[nt][1] - __bfloat162float(h1));
        plB[nt] = packbf2(acc[nt][2] - __bfloat162float(h2), acc[nt][3] - __bfloat162float(h3));
    }

    // ---- PV: out[64q,64d] partials over this warp's 64 j's ----
    float av[8][4];
    #pragma unroll
    for (int nt = 0; nt < 8; nt++) { av[nt][0]=0.f; av[nt][1]=0.f; av[nt][2]=0.f; av[nt][3]=0.f; }

    #pragma unroll
    for (int k = 0; k < 4; k++) {
        u32 aH[4] = { phA[2*k], phB[2*k], phA[2*k+1], phB[2*k+1] };
        u32 aL[4] = { plA[2*k], plB[2*k], plA[2*k+1], plB[2*k+1] };
        int vrow = n0 + 16 * k + ((g & 1) << 3) + lr;
        #pragma unroll
        for (int p = 0; p < 4; p++) {
            u32 voff = swz(vrow, 2 * p + (g >> 1));
            u32 bH[4], bL[4];
            ldsm_x4t(bH, kb + SM_VHI + voff);
            ldsm_x4t(bL, kb + SM_VLO + voff);
            mma_bf16(av[2*p],   aH, bH[0], bH[1]);
            mma_bf16(av[2*p+1], aH, bH[2], bH[3]);
            mma_bf16(av[2*p],   aH, bL[0], bL[1]);
            mma_bf16(av[2*p+1], aH, bL[2], bL[3]);
            mma_bf16(av[2*p],   aL, bH[0], bH[1]);
            mma_bf16(av[2*p+1], aL, bH[2], bH[3]);
        }
    }

    // ---- combine warp-pair partials, normalize, store ----
    if (wn == 1) {
        #pragma unroll
        for (int nt = 0; nt < 8; nt++) {
            int c0 = 8 * nt + 2 * (lane & 3);
            po[rA * POSTR + c0]     = av[nt][0];
            po[rA * POSTR + c0 + 1] = av[nt][1];
            po[rB * POSTR + c0]     = av[nt][2];
            po[rB * POSTR + c0 + 1] = av[nt][3];
        }
    }
    __syncthreads();
    if (wn == 0) {
        #pragma unroll
        for (int nt = 0; nt < 8; nt++) {
            int c0 = 8 * nt + 2 * (lane & 3);
            po[rA * POSTR + c0]     = (av[nt][0] + po[rA * POSTR + c0])     * invsA;
            po[rA * POSTR + c0 + 1] = (av[nt][1] + po[rA * POSTR + c0 + 1]) * invsA;
            po[rB * POSTR + c0]     = (av[nt][2] + po[rB * POSTR + c0])     * invsB;
            po[rB * POSTR + c0 + 1] = (av[nt][3] + po[rB * POSTR + c0 + 1]) * invsB;
        }
        if ((lane & 3) == 0) {
            g_logits[(Bq * NHASH + nh) * TLEN + tiA] = lseA;
            g_logits[(Bq * NHASH + nh) * TLEN + tiB] = lseB;
        }
    }
    __syncthreads();

    // coalesced store of the 64x64 output tile
    for (int i = tid; i < 64 * 16; i += 256) {
        int row = i >> 4, f = (i & 15) << 2;
        size_t orow = ((size_t)((Bq * NHASH + nh) * TLEN + stk[row])) * E;
        *(float4*)&g_o[orow + f] = *(const float4*)&po[row * POSTR + f];
    }
}

// ---------------- combine (unchanged from R5) ----------------
__global__ void combine_kernel(float* __restrict__ out) {
    int gid = blockIdx.x * blockDim.x + threadIdx.x;
    int d4 = (gid & 15) << 2;
    int token = gid >> 4;
    int B = token >> 12, t = token & (TLEN - 1);

    float l[NHASH];
    float mx = -INFINITY;
    #pragma unroll
    for (int nh = 0; nh < NHASH; nh++) {
        l[nh] = g_logits[(B * NHASH + nh) * TLEN + t];
        mx = fmaxf(mx, l[nh]);
    }
    float s = 0.f;
    #pragma unroll
    for (int nh = 0; nh < NHASH; nh++) { l[nh] = __expf(l[nh] - mx); s += l[nh]; }
    float inv = 1.f / s;
    float4 acc = make_float4(0.f, 0.f, 0.f, 0.f);
    #pragma unroll
    for (int nh = 0; nh < NHASH; nh++) {
        float wgt = l[nh] * inv;
        float4 o4 = *(const float4*)&g_o[((size_t)((B * NHASH + nh) * TLEN + t)) * E + d4];
        acc.x = fmaf(wgt, o4.x, acc.x);
        acc.y = fmaf(wgt, o4.y, acc.y);
        acc.z = fmaf(wgt, o4.z, acc.z);
        acc.w = fmaf(wgt, o4.w, acc.w);
    }
    *(float4*)&out[((size_t)token) * E + d4] = acc;
}

extern "C" void kernel_launch(void* const* d_in, const int* in_sizes, int n_in,
                              void* d_out, int out_size) {
    const float* qk  = (const float*)d_in[0];
    // d_in[1] = k is unused by the reference (shared-QK attention)
    const float* v   = (const float*)d_in[2];
    const float* rot = (const float*)d_in[3];
    float* out = (float*)d_out;

    const int hash_smem = (256 * STR + 64 * STR) * (int)sizeof(float);
    cudaFuncSetAttribute(attn_kernel, cudaFuncAttributeMaxDynamicSharedMemorySize, ATTN_SMEM);
    cudaFuncSetAttribute(hash_kernel, cudaFuncAttributeMaxDynamicSharedMemorySize, hash_smem);

    zero_counts_kernel<<<32, 256>>>();
    hash_kernel<<<NB * 64, 256, hash_smem>>>(qk, rot);
    scan_kernel<<<NB, NGBUCK>>>();
    scatter_kernel<<<NB * NHASH, 256>>>();
    attn_kernel<<<NB * CHUNKS, 256, ATTN_SMEM>>>(qk, v);
    combine_kernel<<<NB * TLEN * E / 4 / 256, 256>>>(out);
}

// round 8
// speedup vs baseline: 2.1103x; 1.0520x over previous
#include <cuda_runtime.h>
#include <cuda_bf16.h>
#include <cuda_fp16.h>
#include <stdint.h>
#include <cstdint>
#include <math.h>

// Problem constants
#define NB 16        // B = b*h
#define TLEN 4096    // sequence length
#define NHASH 8
#define NBUCK 64     // local buckets per round
#define NGBUCK 512   // global buckets per B-row
#define CHUNKS 512   // chunks per B-row
#define CS 64        // chunk size
#define E 64         // head dim
#define STR 68       // smem row stride (floats) for hash kernel

typedef unsigned int u32;

// Scratch (device globals — no allocations allowed)
__device__ unsigned char g_buckets[NB * NHASH * TLEN];
__device__ int    g_counts [NB * NGBUCK];
__device__ int    g_offsets[NB * NGBUCK];
__device__ int    g_st     [NB * NHASH * TLEN];
__device__ float  g_logits [NB * NHASH * TLEN];
__device__ __half g_o      [(size_t)NB * NHASH * TLEN * E];   // 64MB (fp16 per-round outputs)

__global__ void zero_counts_kernel() {
    int i = blockIdx.x * blockDim.x + threadIdx.x;
    if (i < NB * NGBUCK) g_counts[i] = 0;
}

// ---------------- hash ----------------
__global__ void __launch_bounds__(256, 2) hash_kernel(const float* __restrict__ qk,
                                                      const float* __restrict__ rot,
                                                      int Boff) {
    extern __shared__ float hsm[];
    float* srot = hsm;               // 256 rows x STR
    float* sq   = srot + 256 * STR;  // 64 tokens x STR

    int tid = threadIdx.x;
    int B  = (blockIdx.x >> 6) + Boff;
    int t0 = (blockIdx.x & 63) << 6;
    int b = B >> 3, hh = B & 7;

    for (int idx = tid; idx < 64 * NHASH * 32; idx += 256) {
        int e = idx >> 8, r = idx & 255;
        srot[r * STR + e] = rot[idx];
    }
    for (int idx = tid; idx < 64 * 16; idx += 256) {
        int tok = idx >> 4, e4 = (idx & 15) << 2;
        const float* q = qk + (((size_t)(b * TLEN + t0 + tok)) * 8 + hh) * E;
        *(float4*)&sq[tok * STR + e4] = *(const float4*)&q[e4];
    }
    __syncthreads();

    int w = tid >> 5, lane = tid & 31;
    int r0 = w * 8;

    for (int nh = 0; nh < NHASH; nh++) {
        float acc[8];
        #pragma unroll
        for (int r = 0; r < 8; r++) acc[r] = 0.f;
        const float* rrow = &srot[(nh * 32 + lane) * STR];
        #pragma unroll 4
        for (int e4 = 0; e4 < 64; e4 += 4) {
            float4 rv = *(const float4*)&rrow[e4];
            #pragma unroll
            for (int r = 0; r < 8; r++) {
                float4 qv = *(const float4*)&sq[(r0 + r) * STR + e4];
                acc[r] = fmaf(qv.x, rv.x, fmaf(qv.y, rv.y, fmaf(qv.z, rv.z, fmaf(qv.w, rv.w, acc[r]))));
            }
        }
        #pragma unroll
        for (int r = 0; r < 8; r++) {
            float a = acc[r];
            float bestv; int besti;
            if (-a > a) { bestv = -a; besti = lane + 32; }
            else        { bestv =  a; besti = lane; }
            #pragma unroll
            for (int off = 16; off; off >>= 1) {
                float ov = __shfl_down_sync(0xffffffffu, bestv, off);
                int   oi = __shfl_down_sync(0xffffffffu, besti, off);
                if (ov > bestv || (ov == bestv && oi < besti)) { bestv = ov; besti = oi; }
            }
            besti = __shfl_sync(0xffffffffu, besti, 0);
            if (lane == 0) {
                int t = t0 + r0 + r;
                g_buckets[(B * NHASH + nh) * TLEN + t] = (unsigned char)besti;
                atomicAdd(&g_counts[B * NGBUCK + nh * NBUCK + besti], 1);
            }
        }
    }
}

__global__ void scan_kernel(int Boff) {
    __shared__ int s[NGBUCK];
    int B = blockIdx.x + Boff, tid = threadIdx.x;
    s[tid] = g_counts[B * NGBUCK + tid];
    __syncthreads();
    for (int off = 1; off < NGBUCK; off <<= 1) {
        int v = (tid >= off) ? s[tid - off] : 0;
        __syncthreads();
        s[tid] += v;
        __syncthreads();
    }
    g_offsets[B * NGBUCK + tid] = tid ? s[tid - 1] : 0;
}

__global__ void scatter_kernel(int Boff) {
    int B = (blockIdx.x >> 3) + Boff, nh = blockIdx.x & 7;
    __shared__ int cnt[NBUCK];
    __shared__ int wcnt[8][NBUCK];
    int tid = threadIdx.x, w = tid >> 5, lane = tid & 31;

    if (tid < NBUCK) cnt[tid] = g_offsets[B * NGBUCK + nh * NBUCK + tid];
    const unsigned char* src = &g_buckets[(B * NHASH + nh) * TLEN];
    int* dst = &g_st[B * (NHASH * TLEN)];

    for (int pass = 0; pass < 16; pass++) {
        wcnt[w][lane] = 0; wcnt[w][lane + 32] = 0;
        __syncthreads();
        int t = pass * 256 + tid;
        int bk = src[t];
        unsigned mask = __match_any_sync(0xffffffffu, bk);
        int rank = __popc(mask & ((1u << lane) - 1u));
        if (rank == 0) wcnt[w][bk] = __popc(mask);
        __syncthreads();
        int pos = cnt[bk] + rank;
        #pragma unroll
        for (int w2 = 0; w2 < 8; w2++)
            if (w2 < w) pos += wcnt[w2][bk];
        dst[pos] = t;
        __syncthreads();
        if (tid < NBUCK) {
            int s = 0;
            #pragma unroll
            for (int w2 = 0; w2 < 8; w2++) s += wcnt[w2][tid];
            cnt[tid] += s;
        }
        __syncthreads();
    }
}

// ---------------- tensor-core attention ----------------
#define SM_KLO 16384
#define SM_VHI 32768
#define SM_VLO 49152
#define SM_PO  65536
#define SM_INV 82944
#define SM_RDM 83456
#define SM_RDS 83968
#define SM_STK 84480
#define ATTN_SMEM 84992
#define POSTR 68

__device__ __forceinline__ u32 swz(int row, int chunk) {
    return (u32)(row * 128 + (((chunk ^ (row & 7)) & 7) << 4));
}
__device__ __forceinline__ void ldsm_x4(u32* r, u32 addr) {
    asm volatile("ldmatrix.sync.aligned.m8n8.x4.shared.b16 {%0,%1,%2,%3}, [%4];"
                 : "=r"(r[0]), "=r"(r[1]), "=r"(r[2]), "=r"(r[3]) : "r"(addr));
}
__device__ __forceinline__ void ldsm_x4t(u32* r, u32 addr) {
    asm volatile("ldmatrix.sync.aligned.m8n8.x4.trans.shared.b16 {%0,%1,%2,%3}, [%4];"
                 : "=r"(r[0]), "=r"(r[1]), "=r"(r[2]), "=r"(r[3]) : "r"(addr));
}
__device__ __forceinline__ void mma_bf16(float* d, const u32* a, u32 b0, u32 b1) {
    asm volatile("mma.sync.aligned.m16n8k16.row.col.f32.bf16.bf16.f32 "
                 "{%0,%1,%2,%3},{%4,%5,%6,%7},{%8,%9},{%0,%1,%2,%3};"
                 : "+f"(d[0]), "+f"(d[1]), "+f"(d[2]), "+f"(d[3])
                 : "r"(a[0]), "r"(a[1]), "r"(a[2]), "r"(a[3]), "r"(b0), "r"(b1));
}
__device__ __forceinline__ u32 packbf2(float a, float b) {
    __nv_bfloat162 t = __floats2bfloat162_rn(a, b);   // .x = a (low half)
    return *(u32*)&t;
}

__global__ void __launch_bounds__(256, 2) attn_kernel(const float* __restrict__ qk,
                                                      const float* __restrict__ vv,
                                                      int Boff) {
    extern __shared__ char smem[];
    float* po   = (float*)(smem + SM_PO);
    float* invn = (float*)(smem + SM_INV);
    float* redm = (float*)(smem + SM_RDM);
    float* reds = (float*)(smem + SM_RDS);
    int*   stk  = (int*)  (smem + SM_STK);

    int tid = threadIdx.x;
    int Bq = (blockIdx.x >> 9) + Boff;
    int c  = blockIdx.x & (CHUNKS - 1);
    int cp = (c + CHUNKS - 1) & (CHUNKS - 1);
    int b = Bq >> 3, hh = Bq & 7;
    int nh = c >> 6;

    if (tid < 128) {
        int p = (tid < 64) ? (c * CS + tid) : (cp * CS + tid - 64);
        stk[tid] = g_st[Bq * (NHASH * TLEN) + p];
    }
    __syncthreads();

    // ---- gather + bf16 hi/lo split + key norms ----
    {
        int seg = tid & 7;              // 8-col segment of a row
        #pragma unroll
        for (int pass = 0; pass < 4; pass++) {
            int j = (tid >> 3) + pass * 32;
            size_t base = (((size_t)(b * TLEN + stk[j])) * 8 + hh) * E + seg * 8;
            float4 q0 = *(const float4*)&qk[base];
            float4 q1 = *(const float4*)&qk[base + 4];
            float4 w0 = *(const float4*)&vv[base];
            float4 w1 = *(const float4*)&vv[base + 4];
            u32 off = swz(j, seg);

            float xq[8] = {q0.x,q0.y,q0.z,q0.w,q1.x,q1.y,q1.z,q1.w};
            float xv[8] = {w0.x,w0.y,w0.z,w0.w,w1.x,w1.y,w1.z,w1.w};
            u32 qh[4], ql[4], vh[4], vl[4];
            #pragma unroll
            for (int i = 0; i < 4; i++) {
                __nv_bfloat16 h0 = __float2bfloat16(xq[2*i]);
                __nv_bfloat16 h1 = __float2bfloat16(xq[2*i+1]);
                qh[i] = packbf2(xq[2*i], xq[2*i+1]);
                ql[i] = packbf2(xq[2*i] - __bfloat162float(h0), xq[2*i+1] - __bfloat162float(h1));
                __nv_bfloat16 g0 = __float2bfloat16(xv[2*i]);
                __nv_bfloat16 g1 = __float2bfloat16(xv[2*i+1]);
                vh[i] = packbf2(xv[2*i], xv[2*i+1]);
                vl[i] = packbf2(xv[2*i] - __bfloat162float(g0), xv[2*i+1] - __bfloat162float(g1));
            }
            *(uint4*)(smem + off)          = make_uint4(qh[0],qh[1],qh[2],qh[3]);
            *(uint4*)(smem + SM_KLO + off) = make_uint4(ql[0],ql[1],ql[2],ql[3]);
            *(uint4*)(smem + SM_VHI + off) = make_uint4(vh[0],vh[1],vh[2],vh[3]);
            *(uint4*)(smem + SM_VLO + off) = make_uint4(vl[0],vl[1],vl[2],vl[3]);

            float ss = 0.f;
            #pragma unroll
            for (int i = 0; i < 8; i++) ss = fmaf(xq[i], xq[i], ss);
            ss += __shfl_xor_sync(0xffffffffu, ss, 1);
            ss += __shfl_xor_sync(0xffffffffu, ss, 2);
            ss += __shfl_xor_sync(0xffffffffu, ss, 4);
            if (seg == 0) invn[j] = 1.f / fmaxf(sqrtf(ss), 1e-12f);
        }
    }
    __syncthreads();

    int w = tid >> 5, lane = tid & 31;
    int wm = w & 3, wn = w >> 2;
    int m0 = wm * 16, n0 = wn * 64;
    int g  = lane >> 3, lr = lane & 7;
    u32 kb = (u32)__cvta_generic_to_shared(smem);

    // ---- QK: D[64q,128k] via 3 split MMAs ----
    float acc[8][4];
    #pragma unroll
    for (int nt = 0; nt < 8; nt++) { acc[nt][0]=0.f; acc[nt][1]=0.f; acc[nt][2]=0.f; acc[nt][3]=0.f; }

    #pragma unroll
    for (int ck = 0; ck < 4; ck++) {
        int arow = m0 + ((g & 1) << 3) + lr;
        u32 aoff = swz(arow, 2 * ck + (g >> 1));
        u32 aH[4], aL[4];
        ldsm_x4(aH, kb + aoff);
        ldsm_x4(aL, kb + SM_KLO + aoff);
        #pragma unroll
        for (int p = 0; p < 4; p++) {
            int brow = n0 + 16 * p + ((g >> 1) << 3) + lr;
            u32 boff = swz(brow, 2 * ck + (g & 1));
            u32 bH[4], bL[4];
            ldsm_x4(bH, kb + boff);
            ldsm_x4(bL, kb + SM_KLO + boff);
            mma_bf16(acc[2*p],   aH, bH[0], bH[1]);
            mma_bf16(acc[2*p+1], aH, bH[2], bH[3]);
            mma_bf16(acc[2*p],   aH, bL[0], bL[1]);
            mma_bf16(acc[2*p+1], aH, bL[2], bL[3]);
            mma_bf16(acc[2*p],   aL, bH[0], bH[1]);
            mma_bf16(acc[2*p+1], aL, bH[2], bH[3]);
        }
    }

    // ---- scale by key inv-norm, self-mask, softmax ----
    int rA = m0 + (lane >> 2), rB = rA + 8;
    int tiA = stk[rA], tiB = stk[rB];
    float mA = -INFINITY, mB = -INFINITY;
    #pragma unroll
    for (int nt = 0; nt < 8; nt++) {
        int c0 = n0 + 8 * nt + 2 * (lane & 3);
        float i0 = invn[c0], i1 = invn[c0 + 1];
        int tc0 = stk[c0], tc1 = stk[c0 + 1];
        acc[nt][0] *= i0; acc[nt][1] *= i1; acc[nt][2] *= i0; acc[nt][3] *= i1;
        if (tc0 == tiA) acc[nt][0] = -50000.f;
        if (tc1 == tiA) acc[nt][1] = -50000.f;
        if (tc0 == tiB) acc[nt][2] = -50000.f;
        if (tc1 == tiB) acc[nt][3] = -50000.f;
        mA = fmaxf(mA, fmaxf(acc[nt][0], acc[nt][1]));
        mB = fmaxf(mB, fmaxf(acc[nt][2], acc[nt][3]));
    }
    mA = fmaxf(mA, __shfl_xor_sync(0xffffffffu, mA, 1));
    mA = fmaxf(mA, __shfl_xor_sync(0xffffffffu, mA, 2));
    mB = fmaxf(mB, __shfl_xor_sync(0xffffffffu, mB, 1));
    mB = fmaxf(mB, __shfl_xor_sync(0xffffffffu, mB, 2));

    int ridx = (wm * 2 + wn) * 16 + (lane >> 2);
    int pidx = (wm * 2 + (1 - wn)) * 16 + (lane >> 2);
    if ((lane & 3) == 0) { redm[ridx] = mA; redm[ridx + 8] = mB; }
    __syncthreads();
    mA = fmaxf(mA, redm[pidx]); mB = fmaxf(mB, redm[pidx + 8]);

    float sA = 0.f, sB = 0.f;
    #pragma unroll
    for (int nt = 0; nt < 8; nt++) {
        acc[nt][0] = __expf(acc[nt][0] - mA);
        acc[nt][1] = __expf(acc[nt][1] - mA);
        acc[nt][2] = __expf(acc[nt][2] - mB);
        acc[nt][3] = __expf(acc[nt][3] - mB);
        sA += acc[nt][0] + acc[nt][1];
        sB += acc[nt][2] + acc[nt][3];
    }
    sA += __shfl_xor_sync(0xffffffffu, sA, 1);
    sA += __shfl_xor_sync(0xffffffffu, sA, 2);
    sB += __shfl_xor_sync(0xffffffffu, sB, 1);
    sB += __shfl_xor_sync(0xffffffffu, sB, 2);
    if ((lane & 3) == 0) { reds[ridx] = sA; reds[ridx + 8] = sB; }
    __syncthreads();
    sA += reds[pidx]; sB += reds[pidx + 8];
    float invsA = 1.f / sA, invsB = 1.f / sB;
    float lseA = mA + __logf(sA), lseB = mB + __logf(sB);

    // ---- P -> bf16 hi/lo fragments (stays in registers) ----
    u32 phA[8], phB[8], plA[8], plB[8];
    #pragma unroll
    for (int nt = 0; nt < 8; nt++) {
        __nv_bfloat16 h0 = __float2bfloat16(acc[nt][0]);
        __nv_bfloat16 h1 = __float2bfloat16(acc[nt][1]);
        __nv_bfloat16 h2 = __float2bfloat16(acc[nt][2]);
        __nv_bfloat16 h3 = __float2bfloat16(acc[nt][3]);
        phA[nt] = packbf2(acc[nt][0], acc[nt][1]);
        phB[nt] = packbf2(acc[nt][2], acc[nt][3]);
        plA[nt] = packbf2(acc[nt][0] - __bfloat162float(h0), acc[nt][1] - __bfloat162float(h1));
        plB[nt] = packbf2(acc[nt][2] - __bfloat162float(h2), acc[nt][3] - __bfloat162float(h3));
    }

    // ---- PV: out[64q,64d] partials over this warp's 64 j's ----
    float av[8][4];
    #pragma unroll
    for (int nt = 0; nt < 8; nt++) { av[nt][0]=0.f; av[nt][1]=0.f; av[nt][2]=0.f; av[nt][3]=0.f; }

    #pragma unroll
    for (int k = 0; k < 4; k++) {
        u32 aH[4] = { phA[2*k], phB[2*k], phA[2*k+1], phB[2*k+1] };
        u32 aL[4] = { plA[2*k], plB[2*k], plA[2*k+1], plB[2*k+1] };
        int vrow = n0 + 16 * k + ((g & 1) << 3) + lr;
        #pragma unroll
        for (int p = 0; p < 4; p++) {
            u32 voff = swz(vrow, 2 * p + (g >> 1));
            u32 bH[4], bL[4];
            ldsm_x4t(bH, kb + SM_VHI + voff);
            ldsm_x4t(bL, kb + SM_VLO + voff);
            mma_bf16(av[2*p],   aH, bH[0], bH[1]);
            mma_bf16(av[2*p+1], aH, bH[2], bH[3]);
            mma_bf16(av[2*p],   aH, bL[0], bL[1]);
            mma_bf16(av[2*p+1], aH, bL[2], bL[3]);
            mma_bf16(av[2*p],   aL, bH[0], bH[1]);
            mma_bf16(av[2*p+1], aL, bH[2], bH[3]);
        }
    }

    // ---- combine warp-pair partials, normalize, store ----
    if (wn == 1) {
        #pragma unroll
        for (int nt = 0; nt < 8; nt++) {
            int c0 = 8 * nt + 2 * (lane & 3);
            po[rA * POSTR + c0]     = av[nt][0];
            po[rA * POSTR + c0 + 1] = av[nt][1];
            po[rB * POSTR + c0]     = av[nt][2];
            po[rB * POSTR + c0 + 1] = av[nt][3];
        }
    }
    __syncthreads();
    if (wn == 0) {
        #pragma unroll
        for (int nt = 0; nt < 8; nt++) {
            int c0 = 8 * nt + 2 * (lane & 3);
            po[rA * POSTR + c0]     = (av[nt][0] + po[rA * POSTR + c0])     * invsA;
            po[rA * POSTR + c0 + 1] = (av[nt][1] + po[rA * POSTR + c0 + 1]) * invsA;
            po[rB * POSTR + c0]     = (av[nt][2] + po[rB * POSTR + c0])     * invsB;
            po[rB * POSTR + c0 + 1] = (av[nt][3] + po[rB * POSTR + c0 + 1]) * invsB;
        }
        if ((lane & 3) == 0) {
            g_logits[(Bq * NHASH + nh) * TLEN + tiA] = lseA;
            g_logits[(Bq * NHASH + nh) * TLEN + tiB] = lseB;
        }
    }
    __syncthreads();

    // coalesced fp16 store of the 64x64 output tile
    for (int i = tid; i < 64 * 16; i += 256) {
        int row = i >> 4, f = (i & 15) << 2;
        size_t orow = ((size_t)((Bq * NHASH + nh) * TLEN + stk[row])) * E;
        float4 p4 = *(const float4*)&po[row * POSTR + f];
        __half2 h0 = __floats2half2_rn(p4.x, p4.y);
        __half2 h1 = __floats2half2_rn(p4.z, p4.w);
        *(uint2*)&g_o[orow + f] = make_uint2(*(u32*)&h0, *(u32*)&h1);
    }
}

// ---------------- combine ----------------
__global__ void combine_kernel(float* __restrict__ out) {
    int gid = blockIdx.x * blockDim.x + threadIdx.x;
    int d4 = (gid & 15) << 2;
    int token = gid >> 4;
    int B = token >> 12, t = token & (TLEN - 1);

    float l[NHASH];
    float mx = -INFINITY;
    #pragma unroll
    for (int nh = 0; nh < NHASH; nh++) {
        l[nh] = g_logits[(B * NHASH + nh) * TLEN + t];
        mx = fmaxf(mx, l[nh]);
    }
    float s = 0.f;
    #pragma unroll
    for (int nh = 0; nh < NHASH; nh++) { l[nh] = __expf(l[nh] - mx); s += l[nh]; }
    float inv = 1.f / s;
    float4 acc = make_float4(0.f, 0.f, 0.f, 0.f);
    #pragma unroll
    for (int nh = 0; nh < NHASH; nh++) {
        float wgt = l[nh] * inv;
        uint2 raw = *(const uint2*)&g_o[((size_t)((B * NHASH + nh) * TLEN + t)) * E + d4];
        float2 f01 = __half22float2(*(__half2*)&raw.x);
        float2 f23 = __half22float2(*(__half2*)&raw.y);
        acc.x = fmaf(wgt, f01.x, acc.x);
        acc.y = fmaf(wgt, f01.y, acc.y);
        acc.z = fmaf(wgt, f23.x, acc.z);
        acc.w = fmaf(wgt, f23.y, acc.w);
    }
    *(float4*)&out[((size_t)token) * E + d4] = acc;
}

extern "C" void kernel_launch(void* const* d_in, const int* in_sizes, int n_in,
                              void* d_out, int out_size) {
    const float* qk  = (const float*)d_in[0];
    // d_in[1] = k is unused by the reference (shared-QK attention)
    const float* v   = (const float*)d_in[2];
    const float* rot = (const float*)d_in[3];
    float* out = (float*)d_out;

    const int hash_smem = (256 * STR + 64 * STR) * (int)sizeof(float);
    cudaFuncSetAttribute(attn_kernel, cudaFuncAttributeMaxDynamicSharedMemorySize, ATTN_SMEM);
    cudaFuncSetAttribute(hash_kernel, cudaFuncAttributeMaxDynamicSharedMemorySize, hash_smem);

    // Two-stream fork/join: B-rows 0-7 on the (captured) legacy stream,
    // B-rows 8-15 on a non-blocking side stream. Falls back to fully
    // sequential legacy-stream execution if stream/event creation fails.
    cudaStream_t s2 = 0;
    cudaEvent_t eF = 0, eJ = 0;
    bool forked = false;
    {
        cudaStream_t tmp;
        if (cudaStreamCreateWithFlags(&tmp, cudaStreamNonBlocking) == cudaSuccess) {
            if (cudaEventCreateWithFlags(&eF, cudaEventDisableTiming) == cudaSuccess &&
                cudaEventCreateWithFlags(&eJ, cudaEventDisableTiming) == cudaSuccess) {
                s2 = tmp;
                forked = true;
            }
        }
    }
    cudaStream_t sB = forked ? s2 : (cudaStream_t)0;

    zero_counts_kernel<<<32, 256>>>();
    if (forked) {
        cudaEventRecord(eF, 0);
        cudaStreamWaitEvent(s2, eF, 0);
    }

    hash_kernel<<<(NB / 2) * 64, 256, hash_smem, 0 >>>(qk, rot, 0);
    hash_kernel<<<(NB / 2) * 64, 256, hash_smem, sB>>>(qk, rot, NB / 2);
    scan_kernel<<<NB / 2, NGBUCK, 0, 0 >>>(0);
    scan_kernel<<<NB / 2, NGBUCK, 0, sB>>>(NB / 2);
    scatter_kernel<<<(NB / 2) * NHASH, 256, 0, 0 >>>(0);
    scatter_kernel<<<(NB / 2) * NHASH, 256, 0, sB>>>(NB / 2);
    attn_kernel<<<(NB / 2) * CHUNKS, 256, ATTN_SMEM, 0 >>>(qk, v, 0);
    attn_kernel<<<(NB / 2) * CHUNKS, 256, ATTN_SMEM, sB>>>(qk, v, NB / 2);

    if (forked) {
        cudaEventRecord(eJ, s2);
        cudaStreamWaitEvent(0, eJ, 0);
    }
    combine_kernel<<<NB * TLEN * E / 4 / 256, 256>>>(out);
}